// round 6
// baseline (speedup 1.0000x reference)
#include <cuda_runtime.h>

// B-spline layer, single fused kernel, max-residency version.
// out[b,f] = ((q3*u+q2)*u+q1)*u + q0,  u = 55x - ii, ii = floor(55x) in [0,54],
// q_d[ii,f] = sum_r P[ii][r][d] * C[ii+3+r, f]   (bias folded into q0).
// P = Cox-de Boor basis polynomial coefficients in local coord u, computed on
// the HOST in double (knot-only, deterministic), passed in the const bank.
//
// 256 thr/block, <=32 regs -> 8 blocks/SM = 2048 thr/SM. smem = 28 KB table
// only (fold reads C straight from L2). Grid (128,8): block folds once, then
// streams 32 batch rows with 4-deep load batching.

#define NF 256
#define NBATCH 4096
#define NII 55
#define NTHREADS 256

struct PTab { float p[NII][4][4]; };

// ---------------- host-side knot/coefficient math (double) ----------------
static double knotD_h(int idx) {
    if (idx < 6)  return -0.002 + 0.0005 * (double)(idx - 3);
    if (idx > 61) return 1.001  + 0.0005 * (double)(idx - 62);
    return (double)(idx - 6) / 55.0;
}

static void make_ptab(PTab& T) {
    for (int ii = 0; ii < NII; ++ii) {
        const int j = ii + 6;
        double P[4][4] = {};
        P[0][0] = 1.0;
        const double x0 = (double)ii / 55.0;
        const double bs = 1.0 / 55.0;   // x = x0 + bs*u
        for (int k = 1; k <= 3; ++k) {
            double Q[4][4] = {};
            for (int r = 0; r <= k; ++r) {
                const int i = j - k + r;
                if (r >= 1) {
                    const double inv = 1.0 / (knotD_h(i + k) - knotD_h(i));
                    const double a = (x0 - knotD_h(i)) * inv;
                    const double b = bs * inv;
                    for (int d = 0; d < 4; ++d) {
                        Q[r][d] += a * P[r - 1][d];
                        if (d > 0) Q[r][d] += b * P[r - 1][d - 1];
                    }
                }
                if (r <= k - 1) {
                    const double inv = 1.0 / (knotD_h(i + k + 1) - knotD_h(i + 1));
                    const double a = (knotD_h(i + k + 1) - x0) * inv;
                    const double b = -bs * inv;
                    for (int d = 0; d < 4; ++d) {
                        Q[r][d] += a * P[r][d];
                        if (d > 0) Q[r][d] += b * P[r][d - 1];
                    }
                }
            }
            for (int r = 0; r < 4; ++r)
                for (int d = 0; d < 4; ++d) P[r][d] = Q[r][d];
        }
        for (int r = 0; r < 4; ++r)
            for (int d = 0; d < 4; ++d) T.p[ii][r][d] = (float)P[r][d];
    }
}

// --------------------------------- kernel ---------------------------------
__global__ __launch_bounds__(NTHREADS, 8) void BSL_25898652795515_kernel(
    const PTab T,                     // 3.5 KB const bank
    const float* __restrict__ X,      // (4096, 256)
    const float* __restrict__ C,      // (64, 256)
    const float* __restrict__ bias,   // (256,)
    float* __restrict__ out)          // (4096, 256)
{
    __shared__ float4 sT[NII * 32];   // 28 KB folded coefficient tile

    const int f0   = blockIdx.y * 32;
    const int row0 = blockIdx.x * 32;
    const int tid  = threadIdx.x;
    const int lane = tid & 31;
    const int wrp  = tid >> 5;        // 0..7
    const int f    = f0 + lane;

    // ---- fold: sT[ii*32+ln].d = sum_r P[ii][r][d] * C[(ii+3+r)*NF + f0+ln]
    // ii = o>>5 warp-uniform -> P reads take the uniform (LDCU) const port.
    // 4 coalesced, mutually independent LDGs per element -> deep MLP.
    for (int o = tid; o < NII * 32; o += NTHREADS) {
        const int ii = o >> 5;
        const int ln = o & 31;
        const float c0 = __ldg(&C[(ii + 3) * NF + f0 + ln]);
        const float c1 = __ldg(&C[(ii + 4) * NF + f0 + ln]);
        const float c2 = __ldg(&C[(ii + 5) * NF + f0 + ln]);
        const float c3 = __ldg(&C[(ii + 6) * NF + f0 + ln]);
        float4 q;
        q.x = fmaf(T.p[ii][0][0], c0, fmaf(T.p[ii][1][0], c1,
              fmaf(T.p[ii][2][0], c2, fmaf(T.p[ii][3][0], c3,
              __ldg(&bias[f0 + ln])))));
        q.y = fmaf(T.p[ii][0][1], c0, fmaf(T.p[ii][1][1], c1,
              fmaf(T.p[ii][2][1], c2, T.p[ii][3][1] * c3)));
        q.z = fmaf(T.p[ii][0][2], c0, fmaf(T.p[ii][1][2], c1,
              fmaf(T.p[ii][2][2], c2, T.p[ii][3][2] * c3)));
        q.w = fmaf(T.p[ii][0][3], c0, fmaf(T.p[ii][1][3], c1,
              fmaf(T.p[ii][2][3], c2, T.p[ii][3][3] * c3)));
        sT[o] = q;
    }
    __syncthreads();

    // ---- stream 32 rows: 4 rows/thread, all loads batched (MLP = 4) ----
    float xv[4];
    #pragma unroll
    for (int k = 0; k < 4; ++k)
        xv[k] = X[(row0 + k * 8 + wrp) * NF + f];

    #pragma unroll
    for (int k = 0; k < 4; ++k) {
        const float xs = xv[k] * 55.0f;
        int ii = min((int)xs, 54);    // x >= 0 -> trunc == floor
        const float u = xs - (float)ii;
        // LDS.128: bank = (ii*128 + 4*lane) % 32 = 4*lane % 32 -> conflict-free
        const float4 c = sT[ii * 32 + lane];
        out[(row0 + k * 8 + wrp) * NF + f] =
            fmaf(fmaf(fmaf(c.w, u, c.z), u, c.y), u, c.x);
    }
}

extern "C" void kernel_launch(void* const* d_in, const int* in_sizes, int n_in,
                              void* d_out, int out_size) {
    const float* x    = (const float*)d_in[0];   // (4096, 256)
    const float* ctrl = (const float*)d_in[1];   // (64, 256)
    const float* bias = (const float*)d_in[2];   // (256,)
    float* out = (float*)d_out;

    PTab T;
    make_ptab(T);   // host double math, knot-only, deterministic

    dim3 grid(NBATCH / 32, NF / 32);   // (128, 8) = 1024 blocks, ~7/SM, 1 wave
    BSL_25898652795515_kernel<<<grid, NTHREADS>>>(T, x, ctrl, bias, out);
}